// round 14
// baseline (speedup 1.0000x reference)
#include <cuda_runtime.h>
#include <cuda_bf16.h>
#include <math.h>
#include <stdint.h>

#define BATCH 8
#define HEADS 8
#define LQ 512
#define LKK 512
#define DKK 64
#define NC 5
#define HD 512            // HEADS*DKK
#define KFLAT 262144      // HEADS*LKK*DKK
#define BH (BATCH*HEADS)
#define FS_ELEMS ((size_t)BH*LQ*LKK)   // 16777216
#define NCH 256           // ck chunks (one block each, all 8 batches per block)

// scratch (no allocations allowed) — all 16B-aligned: cp.async/float4 targets
__device__ float g_part[NCH*BATCH*NC];   // [ch][b*5+c]
__device__ __align__(16) uint2 gQhi[(size_t)BH*LQ*DKK/4];   // Q pre-scaled by 1/8
__device__ __align__(16) uint2 gQlo[(size_t)BH*LQ*DKK/4];
__device__ __align__(16) uint2 gKhi[(size_t)BH*LKK*DKK/4];
__device__ __align__(16) uint2 gKlo[(size_t)BH*LKK*DKK/4];
// per-h means B-matrix (16 rows x 64 cols bf16), hi/lo planes
__device__ __align__(16) uint2 g_meansB_hi[2048];
__device__ __align__(16) uint2 g_meansB_lo[2048];

__device__ __forceinline__ uint32_t smem_u32(const void* p) {
    uint32_t a;
    asm("{ .reg .u64 t; cvta.to.shared.u64 t, %1; cvt.u32.u64 %0, t; }"
        : "=r"(a) : "l"(p));
    return a;
}
__device__ __forceinline__ uint32_t pack_bf2(__nv_bfloat16 a, __nv_bfloat16 b) {
    __nv_bfloat162 t(a, b);
    return *reinterpret_cast<uint32_t*>(&t);
}
__device__ __forceinline__ void split4(float4 v, uint2& hi, uint2& lo) {
    float f[4] = {v.x, v.y, v.z, v.w};
    __nv_bfloat16 h[4], l[4];
    #pragma unroll
    for (int i = 0; i < 4; i++) {
        h[i] = __float2bfloat16_rn(f[i]);
        l[i] = __float2bfloat16_rn(f[i] - __bfloat162float(h[i]));
    }
    hi.x = pack_bf2(h[0], h[1]); hi.y = pack_bf2(h[2], h[3]);
    lo.x = pack_bf2(l[0], l[1]); lo.y = pack_bf2(l[2], l[3]);
}

// ---------------------------------------------------------------------------
// Stage 1 (fused): blocks [0,256): ck partials + K conversion — each block
// owns one 256-float4 chunk, reads its Wp slice ONCE, loops all 8 batches.
// Blocks [256,768): Q conversion (0.125-prescaled), 4 float4 per thread.
// ---------------------------------------------------------------------------
__global__ __launch_bounds__(256) void prep_kernel(const float* __restrict__ K,
                                                   const float* __restrict__ Wp,
                                                   const float* __restrict__ Q) {
    int blk = blockIdx.x, tid = threadIdx.x;

    if (blk < NCH) {
        int ch = blk;
        int j = ch * 256 + tid;                // float4 index within batch
        int lane = tid & 31, wrp = tid >> 5;

        const float4* w4 = (const float4*)(Wp + (size_t)j * 20);
        float wbuf[20];
        #pragma unroll
        for (int r = 0; r < 5; r++) {
            float4 t = w4[r];
            wbuf[r * 4 + 0] = t.x; wbuf[r * 4 + 1] = t.y;
            wbuf[r * 4 + 2] = t.z; wbuf[r * 4 + 3] = t.w;
        }

        float acc[BATCH * NC];
        #pragma unroll
        for (int i = 0; i < BATCH * NC; i++) acc[i] = 0.f;

        #pragma unroll
        for (int b = 0; b < BATCH; b++) {
            float4 f = ((const float4*)(K + (size_t)b * KFLAT))[j];
            #pragma unroll
            for (int c = 0; c < NC; c++) {
                float a = f.x * wbuf[c];
                a = fmaf(f.y, wbuf[5 + c], a);
                a = fmaf(f.z, wbuf[10 + c], a);
                a = fmaf(f.w, wbuf[15 + c], a);
                acc[b * NC + c] = a;
            }
            uint2 hi, lo;
            split4(f, hi, lo);
            size_t gidx = (size_t)b * (KFLAT / 4) + j;
            gKhi[gidx] = hi;
            gKlo[gidx] = lo;
        }

        __shared__ float sred[BATCH * NC * 256];   // 40 KB, [bc][tid]
        #pragma unroll
        for (int bc = 0; bc < BATCH * NC; bc++)
            sred[bc * 256 + tid] = acc[bc];
        __syncthreads();

        #pragma unroll
        for (int q = 0; q < NC; q++) {
            int bc = wrp * NC + q;
            float s = 0.f;
            #pragma unroll
            for (int k = 0; k < 8; k++)
                s += sred[bc * 256 + lane + 32 * k];
            #pragma unroll
            for (int off = 16; off > 0; off >>= 1)
                s += __shfl_down_sync(0xFFFFFFFFu, s, off);
            if (lane == 0)
                g_part[ch * (BATCH * NC) + bc] = s;
        }
    } else {
        int base = (blk - NCH) * 1024;
        const float4* Qs = (const float4*)Q;
        #pragma unroll
        for (int it = 0; it < 4; it++) {
            int i = base + it * 256 + tid;
            float4 v = Qs[i];
            v.x *= 0.125f; v.y *= 0.125f; v.z *= 0.125f; v.w *= 0.125f;
            uint2 hi, lo;
            split4(v, hi, lo);
            gQhi[i] = hi;
            gQlo[i] = lo;
        }
    }
}

// ---------------------------------------------------------------------------
// Stage 2: single block — softmaxes, loss, argmax, cluster means,
// and the per-h means B-matrices (bf16 hi/lo) for the in-GEMM qcm MMA.
// ---------------------------------------------------------------------------
__global__ void setup_kernel(const float* __restrict__ K,
                             const float* __restrict__ b_proj,
                             const float* __restrict__ W_q,
                             const float* __restrict__ b_q,
                             const float* __restrict__ W_k,
                             const float* __restrict__ b_k,
                             float* __restrict__ out) {
    int tid = threadIdx.x;
    __shared__ float s_ck[BATCH][NC], s_cq[BATCH][NC], s_ckk[BATCH][NC];
    __shared__ float s_mu[NC], s_sig[NC], s_ce[BATCH];
    __shared__ int   s_ind[BATCH];
    __shared__ float s_red[4][BATCH * NC];
    __shared__ float sK[BATCH * HD];                    // 16 KB: K row0 slices
    __shared__ __align__(16) float sMeans[NC * HD];     // 10 KB

    for (int i = tid; i < BATCH * HD; i += 256) {
        int b = i >> 9, j = i & 511;
        sK[i] = K[(size_t)b * KFLAT + j];
    }

    // parallel partial reduction: 160 threads, 4 segments of 64 chunks
    if (tid < 160) {
        int bc = tid % 40, seg = tid / 40;
        float s = 0.f;
        #pragma unroll 8
        for (int ch = seg * 64; ch < seg * 64 + 64; ch++)
            s += g_part[ch * (BATCH * NC) + bc];
        s_red[seg][bc] = s;
    }
    __syncthreads();
    if (tid < BATCH * NC) {
        int b = tid / NC, c = tid % NC;
        s_ck[b][c] = b_proj[c] + s_red[0][tid] + s_red[1][tid]
                   + s_red[2][tid] + s_red[3][tid];
    }
    __syncthreads();

    if (tid < BATCH) {
        int b = tid;
        float vq[NC], vk[NC];
        #pragma unroll
        for (int c = 0; c < NC; c++) {
            float sq = b_q[c], sk = b_k[c];
            #pragma unroll
            for (int j = 0; j < NC; j++) {
                sq += s_ck[b][j] * W_q[j * NC + c];
                sk += s_ck[b][j] * W_k[j * NC + c];
            }
            vq[c] = sq; vk[c] = sk;
        }
        float mq = vq[0], mk = vk[0];
        #pragma unroll
        for (int c = 1; c < NC; c++) { mq = fmaxf(mq, vq[c]); mk = fmaxf(mk, vk[c]); }
        float zq = 0.f, zk = 0.f;
        #pragma unroll
        for (int c = 0; c < NC; c++) {
            vq[c] = expf(vq[c] - mq); zq += vq[c];
            vk[c] = expf(vk[c] - mk); zk += vk[c];
        }
        float best = -3.4e38f; int bi = 0;
        float pmax = -3.4e38f;
        #pragma unroll
        for (int c = 0; c < NC; c++) {
            float pq = vq[c] / zq;
            float pk = vk[c] / zk;
            s_cq[b][c]  = pq;
            s_ckk[b][c] = pk;
            if (pq > best) { best = pq; bi = c; }
            pmax = fmaxf(pmax, pq);
        }
        float z = 0.f;
        #pragma unroll
        for (int c = 0; c < NC; c++) z += expf(s_cq[b][c] - pmax);
        float lse = pmax + logf(z);
        float ce = 0.f;
        #pragma unroll
        for (int c = 0; c < NC; c++) ce -= s_cq[b][c] * (s_cq[b][c] - lse);
        s_ce[b]  = ce;
        s_ind[b] = bi;
    }
    __syncthreads();

    if (tid < NC) {
        int c = tid;
        float mu = 0.f, mk = 0.f;
        #pragma unroll
        for (int b = 0; b < BATCH; b++) { mu += s_cq[b][c]; mk += s_ckk[b][c]; }
        mu *= 0.125f; mk *= 0.125f;
        float var = 0.f;
        #pragma unroll
        for (int b = 0; b < BATCH; b++) {
            float d = s_ckk[b][c] - mk;
            var += d * d;
        }
        var /= 7.0f;
        float sd = sqrtf(var);
        s_mu[c]  = mu;
        s_sig[c] = log1pf(expf(sd));
    }
    __syncthreads();

    if (tid == 0) {
        float lp = 0.f;
        for (int b = 0; b < BATCH; b++)
            for (int c = 0; c < NC; c++) {
                float zz = (s_ckk[b][c] - s_mu[c]) / s_sig[c];
                lp += -0.5f * zz * zz - logf(s_sig[c]) - 0.91893853320467274f;
            }
        lp /= 40.0f;
        float ce = 0.f;
        for (int b = 0; b < BATCH; b++) ce += s_ce[b];
        ce *= 0.125f;
        out[FS_ELEMS] = -lp + ce;
    }
    __syncthreads();

    // means[c][j] = (1/8) * sum_b [inds[b] != c+1] * K[b*KFLAT + j]
    for (int idx = tid; idx < NC * HD; idx += blockDim.x) {
        int c = idx / HD, j = idx % HD;
        float s = 0.f;
        #pragma unroll
        for (int b = 0; b < BATCH; b++)
            if (s_ind[b] != c + 1)
                s += sK[b * HD + j];
        sMeans[idx] = s * 0.125f;
    }
    __syncthreads();

    // per-h means B-matrices: rows 0-7 = means[ccA(h)] m-chunks, 8-15 = ccB(h)
    for (int i = tid; i < 2048; i += 256) {
        int c4 = i & 15, n = (i >> 4) & 15, h = i >> 8;
        int u = h * 163840;
        int cc = (n < 8) ? (u >> 18) : ((u + 131072) >> 18);
        int m = n & 7;
        float4 v = *(const float4*)(sMeans + cc * HD + m * 64 + c4 * 4);
        uint2 hi, lo;
        split4(v, hi, lo);
        g_meansB_hi[i] = hi;
        g_meansB_lo[i] = lo;
    }
}

// ---------------------------------------------------------------------------
// Stage 3: mma.sync bf16-split GEMM, fragment-sharing phases with
// dependency-separated MMA issue:
//   phase 1 = hh + lh (share B_hi): per mt, fire afh over all nt, THEN afl
//             over all nt — dependent accumulator reuses are 4 MMAs apart.
//   phase 2 = hl.
// qcm mini-MMA reuses the warp's own af fragment (rows wm + (wid>>1)*16).
// ---------------------------------------------------------------------------
#define STRIDE 72                       // bf16 elems per smem row (144 B)
#define AH_OFF 0
#define AL_OFF 18432
#define BHI_OFF 36864
#define BLO_OFF 55296
#define MH_OFF 73728                    // means hi: 16 rows x 144 B = 2304
#define ML_OFF 76032                    // means lo
#define QCM_OFF 78336                   // fp32 qcm[128][10] = 5120 B
#define SMEM_BYTES 83456

#define LDSM_X4(r0, r1, r2, r3, addr) \
    asm volatile("ldmatrix.sync.aligned.m8n8.x4.shared.b16 {%0,%1,%2,%3}, [%4];" \
                 : "=r"(r0), "=r"(r1), "=r"(r2), "=r"(r3) : "r"(addr))

#define MMA_BF16(c, a, b) \
    asm volatile("mma.sync.aligned.m16n8k16.row.col.f32.bf16.bf16.f32 " \
                 "{%0,%1,%2,%3}, {%4,%5,%6,%7}, {%8,%9}, {%0,%1,%2,%3};" \
                 : "+f"((c)[0]), "+f"((c)[1]), "+f"((c)[2]), "+f"((c)[3]) \
                 : "r"((a)[0]), "r"((a)[1]), "r"((a)[2]), "r"((a)[3]), \
                   "r"((b)[0]), "r"((b)[1]))

#define CP16(dst, src) \
    asm volatile("cp.async.cg.shared.global [%0], [%1], 16;" \
                 :: "r"(dst), "l"(src))

__global__ __launch_bounds__(256, 2) void hmma_kernel(float* __restrict__ out) {
    extern __shared__ char smem[];
    uint32_t sbase = smem_u32(smem);
    float* sqcm = (float*)(smem + QCM_OFF);
    int tid = threadIdx.x;
    int wid = tid >> 5, lane = tid & 31;
    int qt = blockIdx.x, kt = blockIdx.y, bh = blockIdx.z;

    const char* srcAh = (const char*)(gQhi + ((size_t)bh * LQ + qt * 128) * 16);
    const char* srcAl = (const char*)(gQlo + ((size_t)bh * LQ + qt * 128) * 16);
    const char* srcBh = (const char*)(gKhi + ((size_t)bh * LKK + kt * 128) * 16);
    const char* srcBl = (const char*)(gKlo + ((size_t)bh * LKK + kt * 128) * 16);
    const char* srcMh = (const char*)g_meansB_hi + (bh & 7) * 2048;
    const char* srcMl = (const char*)g_meansB_lo + (bh & 7) * 2048;

    // group 1: Ahi + Bhi + Mhi
    #pragma unroll
    for (int v = tid; v < 2048; v += 256) {
        int plane = v >> 10;
        int idx = v & 1023;
        int row = idx >> 3, c = idx & 7;
        uint32_t dst = sbase + (plane ? BHI_OFF : AH_OFF) + row * 144 + c * 16;
        const char* src = (plane ? srcBh : srcAh) + row * 128 + c * 16;
        CP16(dst, src);
    }
    if (tid < 128) {
        int row = tid >> 3, c = tid & 7;
        CP16(sbase + MH_OFF + row * 144 + c * 16, srcMh + row * 128 + c * 16);
    }
    asm volatile("cp.async.commit_group;");
    // group 2: Alo
    #pragma unroll
    for (int v = tid; v < 1024; v += 256) {
        int row = v >> 3, c = v & 7;
        CP16(sbase + AL_OFF + row * 144 + c * 16, srcAl + row * 128 + c * 16);
    }
    asm volatile("cp.async.commit_group;");
    // group 3: Blo + Mlo
    #pragma unroll
    for (int v = tid; v < 1024; v += 256) {
        int row = v >> 3, c = v & 7;
        CP16(sbase + BLO_OFF + row * 144 + c * 16, srcBl + row * 128 + c * 16);
    }
    if (tid < 128) {
        int row = tid >> 3, c = tid & 7;
        CP16(sbase + ML_OFF + row * 144 + c * 16, srcMl + row * 128 + c * 16);
    }
    asm volatile("cp.async.commit_group;");

    int wm = (wid & 1) * 64;
    int wn = (wid >> 1) * 32;
    int mtw = wid >> 1;                 // mt slice whose rows this warp's mini covers
    int arow = lane & 15;
    int akd  = (lane >> 4) << 3;
    int brow = (lane & 7) | ((lane >> 4) << 3);
    int bkd  = lane & 8;
    int g = lane >> 2, q4 = lane & 3;

    float acc[4][4][4];
    #pragma unroll
    for (int mt = 0; mt < 4; mt++)
        #pragma unroll
        for (int nt = 0; nt < 4; nt++)
            #pragma unroll
            for (int r = 0; r < 4; r++) acc[mt][nt][r] = 0.f;
    float mac0[4] = {0.f, 0.f, 0.f, 0.f};
    float mac1[4] = {0.f, 0.f, 0.f, 0.f};

    // ---- phase 1: hh + lh (need Ahi, Bhi, Mhi, Alo) ----
    asm volatile("cp.async.wait_group 1;");
    __syncthreads();

    #pragma unroll
    for (int ks = 0; ks < 4; ks++) {
        int k0 = ks * 16;
        uint32_t bf[4][2];
        #pragma unroll
        for (int n2 = 0; n2 < 2; n2++) {
            uint32_t addr = sbase + BHI_OFF + ((wn + n2 * 16 + brow) * STRIDE + k0 + bkd) * 2;
            LDSM_X4(bf[n2 * 2][0], bf[n2 * 2][1], bf[n2 * 2 + 1][0], bf[n2 * 2 + 1][1], addr);
        }
        uint32_t bfm0[2], bfm1[2];
        {
            uint32_t addrb = sbase + MH_OFF + (brow * STRIDE + k0 + bkd) * 2;
            LDSM_X4(bfm0[0], bfm0[1], bfm1[0], bfm1[1], addrb);
        }
        #pragma unroll
        for (int mt = 0; mt < 4; mt++) {
            uint32_t afh[4], afl[4];
            uint32_t rowoff = ((wm + mt * 16 + arow) * STRIDE + k0 + akd) * 2;
            LDSM_X4(afh[0], afh[1], afh[2], afh[3], sbase + AH_OFF + rowoff);
            LDSM_X4(afl[0], afl[1], afl[2], afl[3], sbase + AL_OFF + rowoff);
            // afh sweep: 4 independent MMAs
            #pragma unroll
            for (int nt = 0; nt < 4; nt++)
                MMA_BF16(acc[mt][nt], afh, bf[nt]);
            if (mt == mtw) {
                MMA_BF16(mac0, afh, bfm0);
                MMA_BF16(mac1, afh, bfm1);
            }
            // afl sweep: each dependent MMA is >=4 issues after its producer
            #pragma unroll
            for (int nt = 0; nt < 4; nt++)
                MMA_BF16(acc[mt][nt], afl, bf[nt]);
            if (mt == mtw) {
                MMA_BF16(mac0, afl, bfm0);
                MMA_BF16(mac1, afl, bfm1);
            }
        }
    }

    // ---- phase 2: hl (need Blo, Mlo) ----
    asm volatile("cp.async.wait_group 0;");
    __syncthreads();

    #pragma unroll
    for (int ks = 0; ks < 4; ks++) {
        int k0 = ks * 16;
        uint32_t bf[4][2];
        #pragma unroll
        for (int n2 = 0; n2 < 2; n2++) {
            uint32_t addr = sbase + BLO_OFF + ((wn + n2 * 16 + brow) * STRIDE + k0 + bkd) * 2;
            LDSM_X4(bf[n2 * 2][0], bf[n2 * 2][1], bf[n2 * 2 + 1][0], bf[n2 * 2 + 1][1], addr);
        }
        uint32_t bfm0[2], bfm1[2];
        {
            uint32_t addrb = sbase + ML_OFF + (brow * STRIDE + k0 + bkd) * 2;
            LDSM_X4(bfm0[0], bfm0[1], bfm1[0], bfm1[1], addrb);
        }
        #pragma unroll
        for (int mt = 0; mt < 4; mt++) {
            uint32_t afh[4];
            uint32_t rowoff = ((wm + mt * 16 + arow) * STRIDE + k0 + akd) * 2;
            LDSM_X4(afh[0], afh[1], afh[2], afh[3], sbase + AH_OFF + rowoff);
            #pragma unroll
            for (int nt = 0; nt < 4; nt++)
                MMA_BF16(acc[mt][nt], afh, bf[nt]);
            if (mt == mtw) {
                MMA_BF16(mac0, afh, bfm0);
                MMA_BF16(mac1, afh, bfm1);
            }
        }
    }

    // publish qcm (max over the ccA/ccB halves) for this warp's 16 rows
    {
        int rb = (wid & 1) * 64 + (wid >> 1) * 16;
        sqcm[(rb + g) * 10 + q4 * 2]         = fmaxf(mac0[0], mac1[0]);
        sqcm[(rb + g) * 10 + q4 * 2 + 1]     = fmaxf(mac0[1], mac1[1]);
        sqcm[(rb + g + 8) * 10 + q4 * 2]     = fmaxf(mac0[2], mac1[2]);
        sqcm[(rb + g + 8) * 10 + q4 * 2 + 1] = fmaxf(mac0[3], mac1[3]);
    }
    __syncthreads();

    // epilogue: max with qcm (from smem), store
    #pragma unroll
    for (int mt = 0; mt < 4; mt++) {
        int rl = wm + mt * 16 + g;             // local row
        float2 qv0 = *(const float2*)(sqcm + rl * 10 + q4 * 2);
        float2 qv1 = *(const float2*)(sqcm + (rl + 8) * 10 + q4 * 2);
        float* row0 = out + ((size_t)bh * LQ + qt * 128 + rl) * LKK + kt * 128;
        float* row1 = row0 + 8 * LKK;
        #pragma unroll
        for (int nt = 0; nt < 4; nt++) {
            int c = wn + nt * 8 + q4 * 2;
            float2 o0, o1;
            o0.x = fmaxf(acc[mt][nt][0], qv0.x);
            o0.y = fmaxf(acc[mt][nt][1], qv0.y);
            o1.x = fmaxf(acc[mt][nt][2], qv1.x);
            o1.y = fmaxf(acc[mt][nt][3], qv1.y);
            *(float2*)(row0 + c) = o0;
            *(float2*)(row1 + c) = o1;
        }
    }
}

// ---------------------------------------------------------------------------
extern "C" void kernel_launch(void* const* d_in, const int* in_sizes, int n_in,
                              void* d_out, int out_size) {
    const float* Q  = (const float*)d_in[0];
    const float* K  = (const float*)d_in[1];
    const float* Wp = (const float*)d_in[2];
    const float* bp = (const float*)d_in[3];
    const float* Wq = (const float*)d_in[4];
    const float* bq = (const float*)d_in[5];
    const float* Wk = (const float*)d_in[6];
    const float* bk = (const float*)d_in[7];
    float* out = (float*)d_out;

    cudaFuncSetAttribute(hmma_kernel,
                         cudaFuncAttributeMaxDynamicSharedMemorySize, SMEM_BYTES);

    prep_kernel<<<NCH + 512, 256>>>(K, Wp, Q);
    setup_kernel<<<1, 256>>>(K, bp, Wq, bq, Wk, bk, out);
    hmma_kernel<<<dim3(LQ / 128, LKK / 128, BH), 256, SMEM_BYTES>>>(out);
}

// round 15
// speedup vs baseline: 1.1231x; 1.1231x over previous
#include <cuda_runtime.h>
#include <cuda_bf16.h>
#include <math.h>
#include <stdint.h>

#define BATCH 8
#define HEADS 8
#define LQ 512
#define LKK 512
#define DKK 64
#define NC 5
#define HD 512            // HEADS*DKK
#define KFLAT 262144      // HEADS*LKK*DKK
#define BH (BATCH*HEADS)
#define FS_ELEMS ((size_t)BH*LQ*LKK)   // 16777216
#define NCH 256           // ck chunks (one block each, all 8 batches per block)

// scratch (no allocations allowed) — all 16B-aligned: cp.async/float4 targets
__device__ float g_part[NCH*BATCH*NC];   // [ch][b*5+c]
__device__ int   g_ticket;               // last-block election (reset each run)
__device__ __align__(16) uint2 gQhi[(size_t)BH*LQ*DKK/4];   // Q pre-scaled by 1/8
__device__ __align__(16) uint2 gQlo[(size_t)BH*LQ*DKK/4];
__device__ __align__(16) uint2 gKhi[(size_t)BH*LKK*DKK/4];
__device__ __align__(16) uint2 gKlo[(size_t)BH*LKK*DKK/4];
// per-h means B-matrix (16 rows x 64 cols bf16), hi/lo planes
__device__ __align__(16) uint2 g_meansB_hi[2048];
__device__ __align__(16) uint2 g_meansB_lo[2048];

__device__ __forceinline__ uint32_t smem_u32(const void* p) {
    uint32_t a;
    asm("{ .reg .u64 t; cvta.to.shared.u64 t, %1; cvt.u32.u64 %0, t; }"
        : "=r"(a) : "l"(p));
    return a;
}
__device__ __forceinline__ uint32_t pack_bf2(__nv_bfloat16 a, __nv_bfloat16 b) {
    __nv_bfloat162 t(a, b);
    return *reinterpret_cast<uint32_t*>(&t);
}
__device__ __forceinline__ void split4(float4 v, uint2& hi, uint2& lo) {
    float f[4] = {v.x, v.y, v.z, v.w};
    __nv_bfloat16 h[4], l[4];
    #pragma unroll
    for (int i = 0; i < 4; i++) {
        h[i] = __float2bfloat16_rn(f[i]);
        l[i] = __float2bfloat16_rn(f[i] - __bfloat162float(h[i]));
    }
    hi.x = pack_bf2(h[0], h[1]); hi.y = pack_bf2(h[2], h[3]);
    lo.x = pack_bf2(l[0], l[1]); lo.y = pack_bf2(l[2], l[3]);
}

// ---------------------------------------------------------------------------
// Stage 1 (fused, with last-block setup): blocks [0,256): ck partials + K
// conversion; the LAST ck block to finish (atomic ticket) runs the whole
// setup phase (softmaxes/loss/means/meansB) in-place — no separate launch.
// Blocks [256,768): Q conversion (0.125-prescaled), 4 float4 per thread.
// ---------------------------------------------------------------------------
__global__ __launch_bounds__(256) void prep_kernel(const float* __restrict__ K,
                                                   const float* __restrict__ Wp,
                                                   const float* __restrict__ Q,
                                                   const float* __restrict__ b_proj,
                                                   const float* __restrict__ W_q,
                                                   const float* __restrict__ b_q,
                                                   const float* __restrict__ W_k,
                                                   const float* __restrict__ b_k,
                                                   float* __restrict__ out) {
    // 40 KB buffer: ck path uses all of it as sred[40][256];
    // the elected setup path reuses it as sK[4096] + sMeans[2560].
    __shared__ __align__(16) float sbuf[BATCH * NC * 256];
    __shared__ float s_ck[BATCH][NC], s_cq[BATCH][NC], s_ckk[BATCH][NC];
    __shared__ float s_mu[NC], s_sig[NC], s_ce[BATCH];
    __shared__ float s_red4[4][BATCH * NC];
    __shared__ int   s_ind[BATCH];
    __shared__ int   s_last;

    int blk = blockIdx.x, tid = threadIdx.x;

    if (blk < NCH) {
        int ch = blk;
        int j = ch * 256 + tid;                // float4 index within batch
        int lane = tid & 31, wrp = tid >> 5;

        const float4* w4 = (const float4*)(Wp + (size_t)j * 20);
        float wbuf[20];
        #pragma unroll
        for (int r = 0; r < 5; r++) {
            float4 t = w4[r];
            wbuf[r * 4 + 0] = t.x; wbuf[r * 4 + 1] = t.y;
            wbuf[r * 4 + 2] = t.z; wbuf[r * 4 + 3] = t.w;
        }

        float acc[BATCH * NC];
        #pragma unroll
        for (int i = 0; i < BATCH * NC; i++) acc[i] = 0.f;

        #pragma unroll
        for (int b = 0; b < BATCH; b++) {
            float4 f = ((const float4*)(K + (size_t)b * KFLAT))[j];
            #pragma unroll
            for (int c = 0; c < NC; c++) {
                float a = f.x * wbuf[c];
                a = fmaf(f.y, wbuf[5 + c], a);
                a = fmaf(f.z, wbuf[10 + c], a);
                a = fmaf(f.w, wbuf[15 + c], a);
                acc[b * NC + c] = a;
            }
            uint2 hi, lo;
            split4(f, hi, lo);
            size_t gidx = (size_t)b * (KFLAT / 4) + j;
            gKhi[gidx] = hi;
            gKlo[gidx] = lo;
        }

        #pragma unroll
        for (int bc = 0; bc < BATCH * NC; bc++)
            sbuf[bc * 256 + tid] = acc[bc];
        __syncthreads();

        #pragma unroll
        for (int q = 0; q < NC; q++) {
            int bc = wrp * NC + q;
            float s = 0.f;
            #pragma unroll
            for (int k = 0; k < 8; k++)
                s += sbuf[bc * 256 + lane + 32 * k];
            #pragma unroll
            for (int off = 16; off > 0; off >>= 1)
                s += __shfl_down_sync(0xFFFFFFFFu, s, off);
            if (lane == 0)
                g_part[ch * (BATCH * NC) + bc] = s;
        }

        // ---- last-block election (threadFenceReduction pattern) ----
        __threadfence();
        if (tid == 0) {
            int t = atomicAdd(&g_ticket, 1);
            s_last = (t == NCH - 1) ? 1 : 0;
        }
        __syncthreads();
        if (!s_last) return;

        // =============== elected block: the whole setup phase ===============
        float* sK     = sbuf;            // 4096 floats
        float* sMeans = sbuf + 4096;     // 2560 floats

        __threadfence();                 // acquire side
        for (int i = tid; i < BATCH * HD; i += 256) {
            int b = i >> 9, jj = i & 511;
            sK[i] = K[(size_t)b * KFLAT + jj];
        }

        // parallel partial reduction: 160 threads, 4 segments of 64 chunks
        if (tid < 160) {
            int bc = tid % 40, seg = tid / 40;
            float s = 0.f;
            #pragma unroll 8
            for (int c2 = seg * 64; c2 < seg * 64 + 64; c2++)
                s += g_part[c2 * (BATCH * NC) + bc];
            s_red4[seg][bc] = s;
        }
        __syncthreads();
        if (tid < BATCH * NC) {
            int b = tid / NC, c = tid % NC;
            s_ck[b][c] = b_proj[c] + s_red4[0][tid] + s_red4[1][tid]
                       + s_red4[2][tid] + s_red4[3][tid];
        }
        __syncthreads();

        if (tid < BATCH) {
            int b = tid;
            float vq[NC], vk[NC];
            #pragma unroll
            for (int c = 0; c < NC; c++) {
                float sq = b_q[c], sk = b_k[c];
                #pragma unroll
                for (int jj = 0; jj < NC; jj++) {
                    sq += s_ck[b][jj] * W_q[jj * NC + c];
                    sk += s_ck[b][jj] * W_k[jj * NC + c];
                }
                vq[c] = sq; vk[c] = sk;
            }
            float mq = vq[0], mk = vk[0];
            #pragma unroll
            for (int c = 1; c < NC; c++) { mq = fmaxf(mq, vq[c]); mk = fmaxf(mk, vk[c]); }
            float zq = 0.f, zk = 0.f;
            #pragma unroll
            for (int c = 0; c < NC; c++) {
                vq[c] = expf(vq[c] - mq); zq += vq[c];
                vk[c] = expf(vk[c] - mk); zk += vk[c];
            }
            float best = -3.4e38f; int bi = 0;
            float pmax = -3.4e38f;
            #pragma unroll
            for (int c = 0; c < NC; c++) {
                float pq = vq[c] / zq;
                float pk = vk[c] / zk;
                s_cq[b][c]  = pq;
                s_ckk[b][c] = pk;
                if (pq > best) { best = pq; bi = c; }
                pmax = fmaxf(pmax, pq);
            }
            float z = 0.f;
            #pragma unroll
            for (int c = 0; c < NC; c++) z += expf(s_cq[b][c] - pmax);
            float lse = pmax + logf(z);
            float ce = 0.f;
            #pragma unroll
            for (int c = 0; c < NC; c++) ce -= s_cq[b][c] * (s_cq[b][c] - lse);
            s_ce[b]  = ce;
            s_ind[b] = bi;
        }
        __syncthreads();

        if (tid < NC) {
            int c = tid;
            float mu = 0.f, mk = 0.f;
            #pragma unroll
            for (int b = 0; b < BATCH; b++) { mu += s_cq[b][c]; mk += s_ckk[b][c]; }
            mu *= 0.125f; mk *= 0.125f;
            float var = 0.f;
            #pragma unroll
            for (int b = 0; b < BATCH; b++) {
                float d = s_ckk[b][c] - mk;
                var += d * d;
            }
            var /= 7.0f;
            float sd = sqrtf(var);
            s_mu[c]  = mu;
            s_sig[c] = log1pf(expf(sd));
        }
        __syncthreads();

        if (tid == 0) {
            float lp = 0.f;
            for (int b = 0; b < BATCH; b++)
                for (int c = 0; c < NC; c++) {
                    float zz = (s_ckk[b][c] - s_mu[c]) / s_sig[c];
                    lp += -0.5f * zz * zz - logf(s_sig[c]) - 0.91893853320467274f;
                }
            lp /= 40.0f;
            float ce = 0.f;
            for (int b = 0; b < BATCH; b++) ce += s_ce[b];
            ce *= 0.125f;
            out[FS_ELEMS] = -lp + ce;
        }
        __syncthreads();

        // means[c][j] = (1/8) * sum_b [inds[b] != c+1] * K[b*KFLAT + j]
        for (int idx = tid; idx < NC * HD; idx += 256) {
            int c = idx / HD, jj = idx % HD;
            float s = 0.f;
            #pragma unroll
            for (int b = 0; b < BATCH; b++)
                if (s_ind[b] != c + 1)
                    s += sK[b * HD + jj];
            sMeans[idx] = s * 0.125f;
        }
        __syncthreads();

        // per-h means B-matrices: rows 0-7 = means[ccA(h)], 8-15 = ccB(h)
        for (int i = tid; i < 2048; i += 256) {
            int c4 = i & 15, n = (i >> 4) & 15, h = i >> 8;
            int u = h * 163840;
            int cc = (n < 8) ? (u >> 18) : ((u + 131072) >> 18);
            int m = n & 7;
            float4 v = *(const float4*)(sMeans + cc * HD + m * 64 + c4 * 4);
            uint2 hi, lo;
            split4(v, hi, lo);
            g_meansB_hi[i] = hi;
            g_meansB_lo[i] = lo;
        }
        if (tid == 0) g_ticket = 0;      // reset for next graph replay
    } else {
        int base = (blk - NCH) * 1024;
        const float4* Qs = (const float4*)Q;
        #pragma unroll
        for (int it = 0; it < 4; it++) {
            int i = base + it * 256 + tid;
            float4 v = Qs[i];
            v.x *= 0.125f; v.y *= 0.125f; v.z *= 0.125f; v.w *= 0.125f;
            uint2 hi, lo;
            split4(v, hi, lo);
            gQhi[i] = hi;
            gQlo[i] = lo;
        }
    }
}

// ---------------------------------------------------------------------------
// Stage 2: mma.sync bf16-split GEMM (hh, hl, lh) — exact round-12 version.
// ---------------------------------------------------------------------------
#define STRIDE 72                       // bf16 elems per smem row (144 B)
#define AH_OFF 0
#define AL_OFF 18432
#define BHI_OFF 36864
#define BLO_OFF 55296
#define MH_OFF 73728                    // means hi: 16 rows x 144 B = 2304
#define ML_OFF 76032                    // means lo
#define QCM_OFF 78336                   // fp32 qcm[128][10] = 5120 B
#define SMEM_BYTES 83456

#define LDSM_X4(r0, r1, r2, r3, addr) \
    asm volatile("ldmatrix.sync.aligned.m8n8.x4.shared.b16 {%0,%1,%2,%3}, [%4];" \
                 : "=r"(r0), "=r"(r1), "=r"(r2), "=r"(r3) : "r"(addr))

#define MMA_BF16(c, a, b) \
    asm volatile("mma.sync.aligned.m16n8k16.row.col.f32.bf16.bf16.f32 " \
                 "{%0,%1,%2,%3}, {%4,%5,%6,%7}, {%8,%9}, {%0,%1,%2,%3};" \
                 : "+f"((c)[0]), "+f"((c)[1]), "+f"((c)[2]), "+f"((c)[3]) \
                 : "r"((a)[0]), "r"((a)[1]), "r"((a)[2]), "r"((a)[3]), \
                   "r"((b)[0]), "r"((b)[1]))

#define CP16(dst, src) \
    asm volatile("cp.async.cg.shared.global [%0], [%1], 16;" \
                 :: "r"(dst), "l"(src))

__global__ __launch_bounds__(256, 2) void hmma_kernel(float* __restrict__ out) {
    extern __shared__ char smem[];
    uint32_t sbase = smem_u32(smem);
    float* sqcm = (float*)(smem + QCM_OFF);
    int tid = threadIdx.x;
    int wid = tid >> 5, lane = tid & 31;
    int qt = blockIdx.x, kt = blockIdx.y, bh = blockIdx.z;

    const char* srcAh = (const char*)(gQhi + ((size_t)bh * LQ + qt * 128) * 16);
    const char* srcAl = (const char*)(gQlo + ((size_t)bh * LQ + qt * 128) * 16);
    const char* srcBh = (const char*)(gKhi + ((size_t)bh * LKK + kt * 128) * 16);
    const char* srcBl = (const char*)(gKlo + ((size_t)bh * LKK + kt * 128) * 16);
    const char* srcMh = (const char*)g_meansB_hi + (bh & 7) * 2048;
    const char* srcMl = (const char*)g_meansB_lo + (bh & 7) * 2048;

    // group A: hi planes (main + means)
    #pragma unroll
    for (int v = tid; v < 2048; v += 256) {
        int plane = v >> 10;
        int idx = v & 1023;
        int row = idx >> 3, c = idx & 7;
        uint32_t dst = sbase + (plane ? BHI_OFF : AH_OFF) + row * 144 + c * 16;
        const char* src = (plane ? srcBh : srcAh) + row * 128 + c * 16;
        CP16(dst, src);
    }
    if (tid < 128) {
        int row = tid >> 3, c = tid & 7;
        CP16(sbase + MH_OFF + row * 144 + c * 16, srcMh + row * 128 + c * 16);
    }
    asm volatile("cp.async.commit_group;");
    // group B: lo planes (main + means)
    #pragma unroll
    for (int v = tid; v < 2048; v += 256) {
        int plane = v >> 10;
        int idx = v & 1023;
        int row = idx >> 3, c = idx & 7;
        uint32_t dst = sbase + (plane ? BLO_OFF : AL_OFF) + row * 144 + c * 16;
        const char* src = (plane ? srcBl : srcAl) + row * 128 + c * 16;
        CP16(dst, src);
    }
    if (tid < 128) {
        int row = tid >> 3, c = tid & 7;
        CP16(sbase + ML_OFF + row * 144 + c * 16, srcMl + row * 128 + c * 16);
    }
    asm volatile("cp.async.commit_group;");

    int wm = (wid & 1) * 64;
    int wn = (wid >> 1) * 32;
    int arow = lane & 15;
    int akd  = (lane >> 4) << 3;
    int brow = (lane & 7) | ((lane >> 4) << 3);
    int bkd  = lane & 8;
    int g = lane >> 2, q4 = lane & 3;

    float acc[4][4][4];
    #pragma unroll
    for (int mt = 0; mt < 4; mt++)
        #pragma unroll
        for (int nt = 0; nt < 4; nt++)
            #pragma unroll
            for (int r = 0; r < 4; r++) acc[mt][nt][r] = 0.f;
    float mac0[4] = {0.f, 0.f, 0.f, 0.f};
    float mac1[4] = {0.f, 0.f, 0.f, 0.f};

    uint32_t a_base[2] = {sbase + AH_OFF, sbase + AL_OFF};
    uint32_t b_base[2] = {sbase + BHI_OFF, sbase + BLO_OFF};
    uint32_t m_base[2] = {sbase + MH_OFF, sbase + ML_OFF};
    int pa[3] = {0, 0, 1};   // hh, hl, lh
    int pb[3] = {0, 1, 0};

    // wait for hi planes only, then run the hh pass while lo planes land
    asm volatile("cp.async.wait_group 1;");
    __syncthreads();

    #pragma unroll
    for (int p = 0; p < 3; p++) {
        if (p == 1) {
            asm volatile("cp.async.wait_group 0;");
            __syncthreads();
        }
        uint32_t Ab = a_base[pa[p]];
        uint32_t Bb = b_base[pb[p]];
        uint32_t Mb = m_base[pb[p]];
        #pragma unroll
        for (int ks = 0; ks < 4; ks++) {
            int k0 = ks * 16;
            uint32_t af[4][4];
            #pragma unroll
            for (int mt = 0; mt < 4; mt++) {
                uint32_t addr = Ab + ((wm + mt * 16 + arow) * STRIDE + k0 + akd) * 2;
                LDSM_X4(af[mt][0], af[mt][1], af[mt][2], af[mt][3], addr);
            }
            uint32_t bf[4][2];
            #pragma unroll
            for (int n2 = 0; n2 < 2; n2++) {
                uint32_t addr = Bb + ((wn + n2 * 16 + brow) * STRIDE + k0 + bkd) * 2;
                LDSM_X4(bf[n2 * 2][0], bf[n2 * 2][1],
                        bf[n2 * 2 + 1][0], bf[n2 * 2 + 1][1], addr);
            }
            #pragma unroll
            for (int mt = 0; mt < 4; mt++)
                #pragma unroll
                for (int nt = 0; nt < 4; nt++)
                    MMA_BF16(acc[mt][nt], af[mt], bf[nt]);

            // fused qcm mini-MMA: this warp's 16-row slice vs means block
            {
                uint32_t afm[4];
                uint32_t addr = Ab + ((wid * 16 + arow) * STRIDE + k0 + akd) * 2;
                LDSM_X4(afm[0], afm[1], afm[2], afm[3], addr);
                uint32_t bfm0[2], bfm1[2];
                uint32_t addrb = Mb + (brow * STRIDE + k0 + bkd) * 2;
                LDSM_X4(bfm0[0], bfm0[1], bfm1[0], bfm1[1], addrb);
                MMA_BF16(mac0, afm, bfm0);
                MMA_BF16(mac1, afm, bfm1);
            }
        }
    }

    // publish qcm (max over the ccA/ccB halves) for this warp's 16 rows
    {
        int rb = wid * 16;
        sqcm[(rb + g) * 10 + q4 * 2]         = fmaxf(mac0[0], mac1[0]);
        sqcm[(rb + g) * 10 + q4 * 2 + 1]     = fmaxf(mac0[1], mac1[1]);
        sqcm[(rb + g + 8) * 10 + q4 * 2]     = fmaxf(mac0[2], mac1[2]);
        sqcm[(rb + g + 8) * 10 + q4 * 2 + 1] = fmaxf(mac0[3], mac1[3]);
    }
    __syncthreads();

    // epilogue: max with qcm (from smem), store
    #pragma unroll
    for (int mt = 0; mt < 4; mt++) {
        int rl = wm + mt * 16 + g;             // local row
        float2 qv0 = *(const float2*)(sqcm + rl * 10 + q4 * 2);
        float2 qv1 = *(const float2*)(sqcm + (rl + 8) * 10 + q4 * 2);
        float* row0 = out + ((size_t)bh * LQ + qt * 128 + rl) * LKK + kt * 128;
        float* row1 = row0 + 8 * LKK;
        #pragma unroll
        for (int nt = 0; nt < 4; nt++) {
            int c = wn + nt * 8 + q4 * 2;
            float2 o0, o1;
            o0.x = fmaxf(acc[mt][nt][0], qv0.x);
            o0.y = fmaxf(acc[mt][nt][1], qv0.y);
            o1.x = fmaxf(acc[mt][nt][2], qv1.x);
            o1.y = fmaxf(acc[mt][nt][3], qv1.y);
            *(float2*)(row0 + c) = o0;
            *(float2*)(row1 + c) = o1;
        }
    }
}

// ---------------------------------------------------------------------------
extern "C" void kernel_launch(void* const* d_in, const int* in_sizes, int n_in,
                              void* d_out, int out_size) {
    const float* Q  = (const float*)d_in[0];
    const float* K  = (const float*)d_in[1];
    const float* Wp = (const float*)d_in[2];
    const float* bp = (const float*)d_in[3];
    const float* Wq = (const float*)d_in[4];
    const float* bq = (const float*)d_in[5];
    const float* Wk = (const float*)d_in[6];
    const float* bk = (const float*)d_in[7];
    float* out = (float*)d_out;

    cudaFuncSetAttribute(hmma_kernel,
                         cudaFuncAttributeMaxDynamicSharedMemorySize, SMEM_BYTES);

    prep_kernel<<<NCH + 512, 256>>>(K, Wp, Q, bp, Wq, bq, Wk, bk, out);
    hmma_kernel<<<dim3(LQ / 128, LKK / 128, BH), 256, SMEM_BYTES>>>(out);
}